// round 3
// baseline (speedup 1.0000x reference)
#include <cuda_runtime.h>

#define VOCAB  200000
#define DIM    128
#define NPOS   10
#define NNEG   64
#define NCTX   (NPOS + NNEG)       // 74
#define NROWS  (1 + NPOS + NNEG)   // 75
#define VEC_PER_ROW (VOCAB / 4)    // 50000
#define BATCH  4
#define THREADS 256

// Scratch (alloc-free rule: __device__ globals).
__device__ int g_idx[NROWS];
__device__ unsigned int g_count = 0;

// Numerically stable log_sigmoid(x) = -softplus(-x)
__device__ __forceinline__ float log_sigmoidf(float x) {
    return (x >= 0.0f) ? -log1pf(expf(-x)) : (x - log1pf(expf(x)));
}

// ---------------------------------------------------------------------------
// Fused kernel:
//  Phase 1 (all blocks): stream the 60 MB of one-hot data, recover indices.
//  Phase 2 (last block to finish): gather embeddings, 74 dots, log_sigmoid,
//  single plain store of the scalar. No second launch.
// ---------------------------------------------------------------------------
__global__ void skipgram_fused(const float4* __restrict__ center,
                               const float4* __restrict__ pos,
                               const float4* __restrict__ neg,
                               const float*  __restrict__ inE,   // [DIM, VOCAB]
                               const float*  __restrict__ outE,  // [VOCAB, DIM]
                               float* __restrict__ out) {
    const int tid = threadIdx.x;

    // ---- Phase 1: streaming index recovery -------------------------------
    {
        const long total = (long)NROWS * VEC_PER_ROW;   // 3,750,000 float4
        const long base  = (long)blockIdx.x * (THREADS * BATCH) + tid;
        #pragma unroll
        for (int k = 0; k < BATCH; k++) {
            long i = base + (long)k * THREADS;
            if (i >= total) continue;
            int row = (int)(i / VEC_PER_ROW);
            int vv  = (int)(i - (long)row * VEC_PER_ROW);

            const float4* p;
            if (row == 0)         p = center + vv;
            else if (row <= NPOS) p = pos + (long)(row - 1) * VEC_PER_ROW + vv;
            else                  p = neg + (long)(row - 1 - NPOS) * VEC_PER_ROW + vv;

            float4 x = __ldcs(p);
            if (x.x != 0.0f) g_idx[row] = 4 * vv + 0;
            if (x.y != 0.0f) g_idx[row] = 4 * vv + 1;
            if (x.z != 0.0f) g_idx[row] = 4 * vv + 2;
            if (x.w != 0.0f) g_idx[row] = 4 * vv + 3;
        }
    }

    // ---- Completion handshake (threadFenceReduction pattern) -------------
    __shared__ bool is_last;
    __threadfence();
    __syncthreads();
    if (tid == 0) {
        unsigned int old = atomicAdd(&g_count, 1u);
        is_last = (old == gridDim.x - 1);
    }
    __syncthreads();
    if (!is_last) return;

    // ---- Phase 2: scoring (one block, 8 warps, batched gathers) ----------
    __shared__ int   idx_s[NROWS];
    __shared__ float v[DIM];
    __shared__ float warp_acc[8];

    const int wid  = tid >> 5;
    const int lane = tid & 31;

    if (tid < NROWS) idx_s[tid] = g_idx[tid];
    __syncthreads();

    const int c = idx_s[0];
    if (tid < DIM) v[tid] = inE[(long)tid * VOCAB + c];
    __syncthreads();

    float acc = 0.0f;
    // 8 warps x up to 10 words each; fully unrolled so the compiler batches
    // all gather loads into one in-flight group (MLP ~40 per lane).
    #pragma unroll
    for (int r = 0; r < 10; r++) {
        int w = wid + r * 8;               // 0..79
        if (w < NCTX) {
            const int idx = idx_s[1 + w];
            float dot = 0.0f;
            if (w < NPOS) {
                #pragma unroll
                for (int j = 0; j < DIM / 32; j++) {
                    int d = lane + 32 * j;
                    dot += v[d] * __ldg(&inE[(long)d * VOCAB + idx]);
                }
            } else {
                const float* rrow = outE + (long)idx * DIM;
                #pragma unroll
                for (int j = 0; j < DIM / 32; j++) {
                    int d = lane + 32 * j;
                    dot += v[d] * __ldg(&rrow[d]);
                }
            }
            #pragma unroll
            for (int s = 16; s; s >>= 1)
                dot += __shfl_xor_sync(0xFFFFFFFFu, dot, s);
            if (lane == 0) acc += log_sigmoidf((w < NPOS) ? dot : -dot);
        }
    }
    if (lane == 0) warp_acc[wid] = acc;
    __syncthreads();

    if (tid == 0) {
        float s = 0.0f;
        #pragma unroll
        for (int i = 0; i < 8; i++) s += warp_acc[i];
        *out = -s;
        g_count = 0;   // reset for next graph replay (deterministic)
    }
}

extern "C" void kernel_launch(void* const* d_in, const int* in_sizes, int n_in,
                              void* d_out, int out_size) {
    const float* center = (const float*)d_in[0];   // [VOCAB]
    const float* pos    = (const float*)d_in[1];   // [NPOS, VOCAB]
    const float* neg    = (const float*)d_in[2];   // [NNEG, VOCAB]
    const float* inE    = (const float*)d_in[3];   // [DIM, VOCAB]
    const float* outE   = (const float*)d_in[4];   // [VOCAB, DIM]
    float* out = (float*)d_out;

    const long total_vec = (long)NROWS * VEC_PER_ROW;            // 3,750,000
    const int per_block = THREADS * BATCH;                       // 1024
    int blocks = (int)((total_vec + per_block - 1) / per_block); // 3663

    skipgram_fused<<<blocks, THREADS>>>((const float4*)center,
                                        (const float4*)pos,
                                        (const float4*)neg,
                                        inE, outE, out);
}

// round 4
// speedup vs baseline: 1.1959x; 1.1959x over previous
#include <cuda_runtime.h>

#define VOCAB  200000
#define DIM    128
#define NPOS   10
#define NNEG   64
#define NCTX   (NPOS + NNEG)       // 74
#define NROWS  (1 + NPOS + NNEG)   // 75
#define VEC_PER_ROW (VOCAB / 4)    // 50000 float4 per row
#define BATCH  4
#define THREADS 256
#define PER_BLOCK (THREADS * BATCH)                         // 1024
#define BLOCKS_PER_ROW ((VEC_PER_ROW + PER_BLOCK - 1) / PER_BLOCK)  // 49
#define GRID (NROWS * BLOCKS_PER_ROW)                       // 3675

// Scratch (alloc-free rule: __device__ globals).
__device__ int g_idx[NROWS];
__device__ unsigned int g_count = 0;

// Numerically stable log_sigmoid(x) = -softplus(-x)
__device__ __forceinline__ float log_sigmoidf(float x) {
    return (x >= 0.0f) ? -log1pf(expf(-x)) : (x - log1pf(expf(x)));
}

// ---------------------------------------------------------------------------
// Fused kernel:
//  Phase 1: each block streams a 1024-float4 segment of ONE row (no per-load
//           division, pointer computed once). Rare release-fence only for the
//           <=75 threads that actually store an index.
//  Phase 2: last block to arrive scores inline (74 dots, log_sigmoid, store).
// ---------------------------------------------------------------------------
__global__ void __launch_bounds__(THREADS)
skipgram_fused(const float4* __restrict__ center,
               const float4* __restrict__ pos,
               const float4* __restrict__ neg,
               const float*  __restrict__ inE,   // [DIM, VOCAB]
               const float*  __restrict__ outE,  // [VOCAB, DIM]
               float* __restrict__ out) {
    const int tid = threadIdx.x;

    // ---- Phase 1: streaming index recovery -------------------------------
    bool wrote = false;
    {
        const int row = blockIdx.x / BLOCKS_PER_ROW;
        const int seg = blockIdx.x - row * BLOCKS_PER_ROW;

        const float4* base;
        if (row == 0)         base = center;
        else if (row <= NPOS) base = pos + (long)(row - 1) * VEC_PER_ROW;
        else                  base = neg + (long)(row - 1 - NPOS) * VEC_PER_ROW;

        const int seg_base = seg * PER_BLOCK + tid;
        #pragma unroll
        for (int k = 0; k < BATCH; k++) {
            int vv = seg_base + k * THREADS;
            if (vv < VEC_PER_ROW) {
                float4 x = __ldcs(base + vv);
                if (x.x != 0.0f) { g_idx[row] = 4 * vv + 0; wrote = true; }
                if (x.y != 0.0f) { g_idx[row] = 4 * vv + 1; wrote = true; }
                if (x.z != 0.0f) { g_idx[row] = 4 * vv + 2; wrote = true; }
                if (x.w != 0.0f) { g_idx[row] = 4 * vv + 3; wrote = true; }
            }
        }
    }

    // ---- Completion handshake ---------------------------------------------
    // Release: only the (<=75 grid-wide) writer threads fence.
    if (wrote) __threadfence();
    __shared__ bool is_last;
    __syncthreads();   // orders writer fences before tid0's atomic
    if (tid == 0) {
        unsigned int old = atomicAdd(&g_count, 1u);
        is_last = (old == (unsigned)(GRID - 1));
    }
    __syncthreads();
    if (!is_last) return;
    __threadfence();   // acquire: make all g_idx stores visible to this block

    // ---- Phase 2: scoring (one block, 8 warps, batched gathers) ----------
    __shared__ int   idx_s[NROWS];
    __shared__ float v[DIM];
    __shared__ float warp_acc[8];

    const int wid  = tid >> 5;
    const int lane = tid & 31;

    if (tid < NROWS) idx_s[tid] = g_idx[tid];
    __syncthreads();

    const int c = idx_s[0];
    if (tid < DIM) v[tid] = inE[(long)tid * VOCAB + c];
    __syncthreads();

    float acc = 0.0f;
    #pragma unroll
    for (int r = 0; r < 10; r++) {
        int w = wid + r * 8;               // 0..79
        if (w < NCTX) {
            const int idx = idx_s[1 + w];
            float dot = 0.0f;
            if (w < NPOS) {
                #pragma unroll
                for (int j = 0; j < DIM / 32; j++) {
                    int d = lane + 32 * j;
                    dot += v[d] * __ldg(&inE[(long)d * VOCAB + idx]);
                }
            } else {
                const float* rrow = outE + (long)idx * DIM;
                #pragma unroll
                for (int j = 0; j < DIM / 32; j++) {
                    int d = lane + 32 * j;
                    dot += v[d] * __ldg(&rrow[d]);
                }
            }
            #pragma unroll
            for (int s = 16; s; s >>= 1)
                dot += __shfl_xor_sync(0xFFFFFFFFu, dot, s);
            if (lane == 0) acc += log_sigmoidf((w < NPOS) ? dot : -dot);
        }
    }
    if (lane == 0) warp_acc[wid] = acc;
    __syncthreads();

    if (tid == 0) {
        float s = 0.0f;
        #pragma unroll
        for (int i = 0; i < 8; i++) s += warp_acc[i];
        *out = -s;
        g_count = 0;   // reset for next graph replay (deterministic)
    }
}

extern "C" void kernel_launch(void* const* d_in, const int* in_sizes, int n_in,
                              void* d_out, int out_size) {
    const float* center = (const float*)d_in[0];   // [VOCAB]
    const float* pos    = (const float*)d_in[1];   // [NPOS, VOCAB]
    const float* neg    = (const float*)d_in[2];   // [NNEG, VOCAB]
    const float* inE    = (const float*)d_in[3];   // [DIM, VOCAB]
    const float* outE   = (const float*)d_in[4];   // [VOCAB, DIM]
    float* out = (float*)d_out;

    skipgram_fused<<<GRID, THREADS>>>((const float4*)center,
                                      (const float4*)pos,
                                      (const float4*)neg,
                                      inE, outE, out);
}

// round 5
// speedup vs baseline: 1.2897x; 1.0785x over previous
#include <cuda_runtime.h>

#define VOCAB  200000
#define DIM    128
#define NPOS   10
#define NNEG   64
#define NCTX   (NPOS + NNEG)       // 74
#define NROWS  (1 + NPOS + NNEG)   // 75
#define VEC_PER_ROW (VOCAB / 4)    // 50000 float4 per row
#define TOTAL_VEC (NROWS * VEC_PER_ROW)   // 3,750,000 float4

#define THREADS 256
#define GRID    (148 * 8)          // 1184 blocks = exactly one wave at occ 8
#define CHUNK   3328               // float4 per block; 1184*3328 >= TOTAL_VEC
#define ITERS   (CHUNK / THREADS)  // 13 loads per thread

// Scratch (alloc-free rule: __device__ globals).
__device__ int g_idx[NROWS];
__device__ unsigned int g_count = 0;

// Numerically stable log_sigmoid(x) = -softplus(-x)
__device__ __forceinline__ float log_sigmoidf(float x) {
    return (x >= 0.0f) ? -log1pf(expf(-x)) : (x - log1pf(expf(x)));
}

// ---------------------------------------------------------------------------
// Fused persistent kernel (single wave):
//  Phase 1: each block streams one contiguous 3328-float4 chunk of the
//           concatenated one-hot data (center|pos|neg). A chunk spans at most
//           2 logical rows -> two base pointers computed once, per-load select.
//  Handshake: ONE barrier+atomic per block (amortized over 13 loads/thread).
//  Phase 2: last block scores inline and stores the scalar.
// ---------------------------------------------------------------------------
__global__ void __launch_bounds__(THREADS)
skipgram_fused(const float4* __restrict__ center,
               const float4* __restrict__ pos,
               const float4* __restrict__ neg,
               const float*  __restrict__ inE,   // [DIM, VOCAB]
               const float*  __restrict__ outE,  // [VOCAB, DIM]
               float* __restrict__ out) {
    const int tid = threadIdx.x;

    // Row -> base pointer for that row's float4 data.
    auto row_ptr = [&](int row) -> const float4* {
        if (row <= 0)    return center;
        if (row <= NPOS) return pos + (long)(row - 1) * VEC_PER_ROW;
        int r = row <= NROWS - 1 ? row : NROWS - 1;
        return neg + (long)(r - 1 - NPOS) * VEC_PER_ROW;
    };

    // ---- Phase 1: streaming index recovery -------------------------------
    bool wrote = false;
    {
        const int chunk_base = blockIdx.x * CHUNK;        // global float4 idx
        const int row0   = chunk_base / VEC_PER_ROW;      // once per block
        const int row1   = row0 + 1;
        const int start0 = row0 * VEC_PER_ROW;
        const int start1 = row1 * VEC_PER_ROW;            // also the boundary
        const float4* base0 = row_ptr(row0);
        const float4* base1 = row_ptr(row1);

        #pragma unroll
        for (int k = 0; k < ITERS; k++) {
            int i = chunk_base + tid + k * THREADS;
            if (i < TOTAL_VEC) {
                bool hi = (i >= start1);
                const float4* p = hi ? (base1 + (i - start1))
                                     : (base0 + (i - start0));
                float4 x = __ldcs(p);
                if ((x.x != 0.0f) | (x.y != 0.0f) | (x.z != 0.0f) | (x.w != 0.0f)) {
                    int row = hi ? row1 : row0;
                    int vv  = i - (hi ? start1 : start0);
                    int sub = (x.x != 0.0f) ? 0 : (x.y != 0.0f) ? 1
                            : (x.z != 0.0f) ? 2 : 3;
                    g_idx[row] = 4 * vv + sub;
                    wrote = true;
                }
            }
        }
    }

    // ---- Completion handshake (once per block) ----------------------------
    if (wrote) __threadfence();          // release (rare: <=75 threads total)
    __shared__ bool is_last;
    __syncthreads();                     // orders writer fences before atomic
    if (tid == 0) {
        unsigned int old = atomicAdd(&g_count, 1u);
        is_last = (old == (unsigned)(GRID - 1));
    }
    __syncthreads();
    if (!is_last) return;
    __threadfence();                     // acquire: see all g_idx stores

    // ---- Phase 2: scoring (one block, 8 warps, batched gathers) ----------
    __shared__ int   idx_s[NROWS];
    __shared__ float v[DIM];
    __shared__ float warp_acc[8];

    const int wid  = tid >> 5;
    const int lane = tid & 31;

    if (tid < NROWS) idx_s[tid] = g_idx[tid];
    __syncthreads();

    const int c = idx_s[0];
    if (tid < DIM) v[tid] = inE[(long)tid * VOCAB + c];
    __syncthreads();

    float acc = 0.0f;
    #pragma unroll
    for (int r = 0; r < 10; r++) {
        int w = wid + r * 8;             // 0..79
        if (w < NCTX) {
            const int idx = idx_s[1 + w];
            float dot = 0.0f;
            if (w < NPOS) {
                #pragma unroll
                for (int j = 0; j < DIM / 32; j++) {
                    int d = lane + 32 * j;
                    dot += v[d] * __ldg(&inE[(long)d * VOCAB + idx]);
                }
            } else {
                const float* rrow = outE + (long)idx * DIM;
                #pragma unroll
                for (int j = 0; j < DIM / 32; j++) {
                    int d = lane + 32 * j;
                    dot += v[d] * __ldg(&rrow[d]);
                }
            }
            #pragma unroll
            for (int s = 16; s; s >>= 1)
                dot += __shfl_xor_sync(0xFFFFFFFFu, dot, s);
            if (lane == 0) acc += log_sigmoidf((w < NPOS) ? dot : -dot);
        }
    }
    if (lane == 0) warp_acc[wid] = acc;
    __syncthreads();

    if (tid == 0) {
        float s = 0.0f;
        #pragma unroll
        for (int i = 0; i < 8; i++) s += warp_acc[i];
        *out = -s;
        g_count = 0;   // reset for next graph replay (deterministic)
    }
}

extern "C" void kernel_launch(void* const* d_in, const int* in_sizes, int n_in,
                              void* d_out, int out_size) {
    const float* center = (const float*)d_in[0];   // [VOCAB]
    const float* pos    = (const float*)d_in[1];   // [NPOS, VOCAB]
    const float* neg    = (const float*)d_in[2];   // [NNEG, VOCAB]
    const float* inE    = (const float*)d_in[3];   // [DIM, VOCAB]
    const float* outE   = (const float*)d_in[4];   // [VOCAB, DIM]
    float* out = (float*)d_out;

    skipgram_fused<<<GRID, THREADS>>>((const float4*)center,
                                      (const float4*)pos,
                                      (const float4*)neg,
                                      inE, outE, out);
}